// round 2
// baseline (speedup 1.0000x reference)
#include <cuda_runtime.h>
#include <math.h>

// ---------------- problem constants ----------------
#define BATCH   64
#define HH      56
#define WW_DIM  56
#define CC      128
#define WIN     7
#define SHIFT   3
#define NH      4
#define HD      32
#define NTOK    49              // WIN*WIN
#define NWH     8               // H/WIN
#define NWIN    64              // per image
#define TOTW    (BATCH*NWIN)    // 4096 windows
#define MROWS   (TOTW*NTOK)     // 200704 token rows
#define MLPH    512

// ---------------- scratch (device globals; no allocation allowed) ----------
__device__ float g_hwin[(size_t)MROWS*CC];    // LN1 windowed tokens / reused for LN2 output
__device__ float g_qkv [(size_t)MROWS*3*CC];  // qkv projection
__device__ float g_obuf[(size_t)MROWS*CC];    // attention output (window layout)
__device__ float g_x1  [(size_t)MROWS*CC];    // x + attn branch (image layout)
__device__ float g_act [(size_t)MROWS*MLPH];  // gelu(fc1)

// map (window,tok) -> image row index (same formula forward & reverse: (p+3)%56)
__device__ __forceinline__ int win_to_img(int grow) {
    int w = grow / NTOK, n = grow - w * NTOK;
    int bi = w >> 6, widx = w & 63;
    int r = ((widx >> 3) * WIN + n / WIN + SHIFT) % HH;
    int c = ((widx & 7)  * WIN + n % WIN + SHIFT) % WW_DIM;
    return bi * (HH * WW_DIM) + r * WW_DIM + c;
}

// ---------------- LayerNorm (one warp per 128-ch row) ----------------------
__global__ void __launch_bounds__(256) ln_kernel(
    const float* __restrict__ in, float* __restrict__ out,
    const float* __restrict__ g, const float* __restrict__ b, int gather)
{
    int row  = blockIdx.x * 8 + (threadIdx.x >> 5);
    int lane = threadIdx.x & 31;
    if (row >= MROWS) return;
    int src = gather ? win_to_img(row) : row;

    float4 v = *(const float4*)(in + (size_t)src * CC + lane * 4);
    float s = v.x + v.y + v.z + v.w;
    #pragma unroll
    for (int o = 16; o; o >>= 1) s += __shfl_xor_sync(~0u, s, o);
    float mean = s * (1.f / CC);
    float dx = v.x - mean, dy = v.y - mean, dz = v.z - mean, dw = v.w - mean;
    float vv = dx*dx + dy*dy + dz*dz + dw*dw;
    #pragma unroll
    for (int o = 16; o; o >>= 1) vv += __shfl_xor_sync(~0u, vv, o);
    float rstd = rsqrtf(vv * (1.f / CC) + 1e-5f);

    float4 gg = *(const float4*)(g + lane * 4);
    float4 bb = *(const float4*)(b + lane * 4);
    float4 o4;
    o4.x = dx * rstd * gg.x + bb.x;
    o4.y = dy * rstd * gg.y + bb.y;
    o4.z = dz * rstd * gg.z + bb.z;
    o4.w = dw * rstd * gg.w + bb.w;
    *(float4*)(out + (size_t)row * CC + lane * 4) = o4;
}

// ---------------- tiled SGEMM: out[M,N] = A[M,K] @ W[N,K]^T + bias ---------
// EPI 0: plain (+bias)             -> out[row]
// EPI 1: proj: scatter row to image layout, add shortcut (extra)
// EPI 2: exact GELU(+bias)
// EPI 3: +bias + extra[row] (residual), plain row
#define BM 128
#define BN 128
#define BKC 8

template<int EPI>
__global__ void __launch_bounds__(256) gemm_k(
    const float* __restrict__ A, const float* __restrict__ W,
    const float* __restrict__ bias, float* __restrict__ out,
    const float* __restrict__ extra, int M, int N, int K)
{
    __shared__ float As[BKC][BM];
    __shared__ float Bs[BKC][BN];

    int tid = threadIdx.x;
    int ty = tid >> 4, tx = tid & 15;
    int rowBlock = blockIdx.x * BM;
    int colBlock = blockIdx.y * BN;

    int ar = tid >> 1;            // 0..127 : tile row
    int ak = (tid & 1) * 4;       // 0 or 4 : k chunk

    float acc[8][8];
    #pragma unroll
    for (int i = 0; i < 8; i++)
        #pragma unroll
        for (int j = 0; j < 8; j++) acc[i][j] = 0.f;

    const float* Abase = A + (size_t)(rowBlock + ar) * K + ak;
    const float* Wbase = W + (size_t)(colBlock + ar) * K + ak;

    for (int kt = 0; kt < K; kt += BKC) {
        float4 av = *(const float4*)(Abase + kt);
        float4 wv = *(const float4*)(Wbase + kt);
        As[ak + 0][ar] = av.x; As[ak + 1][ar] = av.y;
        As[ak + 2][ar] = av.z; As[ak + 3][ar] = av.w;
        Bs[ak + 0][ar] = wv.x; Bs[ak + 1][ar] = wv.y;
        Bs[ak + 2][ar] = wv.z; Bs[ak + 3][ar] = wv.w;
        __syncthreads();

        #pragma unroll
        for (int k = 0; k < BKC; k++) {
            float a[8], bb[8];
            *(float4*)(a)      = *(const float4*)&As[k][ty * 8];
            *(float4*)(a + 4)  = *(const float4*)&As[k][ty * 8 + 4];
            *(float4*)(bb)     = *(const float4*)&Bs[k][tx * 8];
            *(float4*)(bb + 4) = *(const float4*)&Bs[k][tx * 8 + 4];
            #pragma unroll
            for (int i = 0; i < 8; i++)
                #pragma unroll
                for (int j = 0; j < 8; j++)
                    acc[i][j] += a[i] * bb[j];
        }
        __syncthreads();
    }

    int grow0 = rowBlock + ty * 8;
    int gcol0 = colBlock + tx * 8;

    #pragma unroll
    for (int i = 0; i < 8; i++) {
        int grow = grow0 + i;
        size_t orow;
        if (EPI == 1) orow = (size_t)win_to_img(grow);
        else          orow = (size_t)grow;
        #pragma unroll
        for (int j = 0; j < 8; j++) {
            int gcol = gcol0 + j;
            float v = acc[i][j] + bias[gcol];
            if (EPI == 0) {
                out[orow * N + gcol] = v;
            } else if (EPI == 1) {
                out[orow * CC + gcol] = extra[orow * CC + gcol] + v;
            } else if (EPI == 2) {
                out[orow * N + gcol] = 0.5f * v * (1.f + erff(v * 0.70710678118654752f));
            } else {
                out[orow * N + gcol] = extra[orow * N + gcol] + v;
            }
        }
    }
}

// ---------------- window attention: one block per (window, head) ----------
__global__ void __launch_bounds__(256) attn_kernel(
    const float* __restrict__ qkv, const float* __restrict__ rpb,
    float* __restrict__ obuf)
{
    int blk = blockIdx.x;
    int w = blk >> 2, h = blk & 3;
    int tid = threadIdx.x;

    __shared__ float qs[NTOK][HD], ks[NTOK][HD], vs[NTOK][HD];
    __shared__ float sc[NTOK][56];

    const float scale = 0.17677669529663687f;  // 1/sqrt(32)
    size_t base = (size_t)w * NTOK * (3 * CC) + h * HD;

    for (int i = tid; i < NTOK * HD; i += 256) {
        int n = i >> 5, d = i & 31;
        size_t off = base + (size_t)n * (3 * CC) + d;
        qs[n][d] = qkv[off] * scale;
        ks[n][d] = qkv[off + CC];
        vs[n][d] = qkv[off + 2 * CC];
    }
    int widx = w & 63;
    int wh = widx >> 3, wwc = widx & 7;
    __syncthreads();

    // scores + relative position bias + shift mask
    // mask regions along each axis: [0,49) -> 0, [49,53) -> 1, [53,56) -> 2
    for (int i = tid; i < NTOK * NTOK; i += 256) {
        int n = i / NTOK, m = i - n * NTOK;
        float s = 0.f;
        #pragma unroll
        for (int d = 0; d < HD; d++) s += qs[n][d] * ks[m][d];
        int ny = n / WIN, nx = n % WIN, my = m / WIN, mx = m % WIN;
        int rpi = (ny - my + WIN - 1) * (2 * WIN - 1) + (nx - mx + WIN - 1);
        s += rpb[rpi * NH + h];
        int rn = wh * WIN + ny, cn = wwc * WIN + nx;
        int rm = wh * WIN + my, cm = wwc * WIN + mx;
        int ln = (rn < 49 ? 0 : (rn < 53 ? 1 : 2)) * 3 + (cn < 49 ? 0 : (cn < 53 ? 1 : 2));
        int lm = (rm < 49 ? 0 : (rm < 53 ? 1 : 2)) * 3 + (cm < 49 ? 0 : (cm < 53 ? 1 : 2));
        if (ln != lm) s -= 100.f;
        sc[n][m] = s;
    }
    __syncthreads();

    // softmax: one warp per row (rows strided by 8)
    int warp = tid >> 5, lane = tid & 31;
    for (int r = warp; r < NTOK; r += 8) {
        float v0 = sc[r][lane];
        float v1 = (lane < 17) ? sc[r][lane + 32] : -1e30f;
        float mx = fmaxf(v0, v1);
        #pragma unroll
        for (int o = 16; o; o >>= 1) mx = fmaxf(mx, __shfl_xor_sync(~0u, mx, o));
        float e0 = expf(v0 - mx);
        float e1 = (lane < 17) ? expf(v1 - mx) : 0.f;
        float sm = e0 + e1;
        #pragma unroll
        for (int o = 16; o; o >>= 1) sm += __shfl_xor_sync(~0u, sm, o);
        float inv = 1.f / sm;
        sc[r][lane] = e0 * inv;
        if (lane < 17) sc[r][lane + 32] = e1 * inv;
    }
    __syncthreads();

    // O = P @ V  -> window-major layout (w, n, C) with head offset
    for (int i = tid; i < NTOK * HD; i += 256) {
        int n = i >> 5, d = i & 31;
        float s = 0.f;
        #pragma unroll
        for (int m = 0; m < NTOK; m++) s += sc[n][m] * vs[m][d];
        obuf[((size_t)w * NTOK + n) * CC + h * HD + d] = s;
    }
}

// ---------------- launch --------------------------------------------------
extern "C" void kernel_launch(void* const* d_in, const int* in_sizes, int n_in,
                              void* d_out, int out_size)
{
    const float* x      = (const float*)d_in[0];
    const float* ln1_g  = (const float*)d_in[1];
    const float* ln1_b  = (const float*)d_in[2];
    const float* qkv_w  = (const float*)d_in[3];
    const float* qkv_b  = (const float*)d_in[4];
    const float* rpb    = (const float*)d_in[5];
    const float* proj_w = (const float*)d_in[6];
    const float* proj_b = (const float*)d_in[7];
    const float* ln2_g  = (const float*)d_in[8];
    const float* ln2_b  = (const float*)d_in[9];
    const float* fc1_w  = (const float*)d_in[10];
    const float* fc1_b  = (const float*)d_in[11];
    const float* fc2_w  = (const float*)d_in[12];
    const float* fc2_b  = (const float*)d_in[13];
    float* out = (float*)d_out;

    float *hwin, *qkvb, *obuf, *x1, *act;
    cudaGetSymbolAddress((void**)&hwin, g_hwin);
    cudaGetSymbolAddress((void**)&qkvb, g_qkv);
    cudaGetSymbolAddress((void**)&obuf, g_obuf);
    cudaGetSymbolAddress((void**)&x1,   g_x1);
    cudaGetSymbolAddress((void**)&act,  g_act);

    // 1) LN1 + cyclic shift + window partition
    ln_kernel<<<MROWS / 8, 256>>>(x, hwin, ln1_g, ln1_b, 1);
    // 2) QKV projection
    gemm_k<0><<<dim3(MROWS / BM, 3), 256>>>(hwin, qkv_w, qkv_b, qkvb, nullptr,
                                            MROWS, 3 * CC, CC);
    // 3) window attention
    attn_kernel<<<TOTW * NH, 256>>>(qkvb, rpb, obuf);
    // 4) proj + window reverse + reverse shift + residual  -> x1 (image layout)
    gemm_k<1><<<dim3(MROWS / BM, 1), 256>>>(obuf, proj_w, proj_b, x1, x,
                                            MROWS, CC, CC);
    // 5) LN2
    ln_kernel<<<MROWS / 8, 256>>>(x1, hwin, ln2_g, ln2_b, 0);
    // 6) fc1 + exact GELU
    gemm_k<2><<<dim3(MROWS / BM, MLPH / BN), 256>>>(hwin, fc1_w, fc1_b, act, nullptr,
                                                    MROWS, MLPH, CC);
    // 7) fc2 + residual -> final output
    gemm_k<3><<<dim3(MROWS / BM, 1), 256>>>(act, fc2_w, fc2_b, out, x1,
                                            MROWS, CC, MLPH);
}

// round 3
// speedup vs baseline: 3.9638x; 3.9638x over previous
#include <cuda_runtime.h>
#include <cuda_bf16.h>
#include <math.h>
#include <stdint.h>

// ---------------- problem constants ----------------
#define BATCH   64
#define HH      56
#define WW_DIM  56
#define CC      128
#define WIN     7
#define SHIFT   3
#define NH      4
#define HD      32
#define NTOK    49
#define TOTW    (BATCH*64)      // 4096 windows
#define MROWS   (TOTW*NTOK)     // 200704 token rows
#define MLPH    512

// ---------------- scratch ----------------
__device__ __nv_bfloat16 g_hwin[(size_t)MROWS*CC];
__device__ __nv_bfloat16 g_qkv [(size_t)MROWS*3*CC];
__device__ __nv_bfloat16 g_obuf[(size_t)MROWS*CC];
__device__ float         g_x1  [(size_t)MROWS*CC];
__device__ __nv_bfloat16 g_act [(size_t)MROWS*MLPH];
__device__ __nv_bfloat16 g_wq [3*CC*CC];
__device__ __nv_bfloat16 g_wp [CC*CC];
__device__ __nv_bfloat16 g_wf1[MLPH*CC];
__device__ __nv_bfloat16 g_wf2[CC*MLPH];

__device__ __forceinline__ int win_to_img(int grow) {
    int w = grow / NTOK, n = grow - w * NTOK;
    int bi = w >> 6, widx = w & 63;
    int r = ((widx >> 3) * WIN + n / WIN + SHIFT) % HH;
    int c = ((widx & 7)  * WIN + n % WIN + SHIFT) % WW_DIM;
    return bi * (HH * WW_DIM) + r * WW_DIM + c;
}

// ---------------- fp32 -> bf16 convert ----------------
__global__ void f2bf_kernel(const float* __restrict__ a, __nv_bfloat16* __restrict__ b, int n) {
    int i = blockIdx.x * blockDim.x + threadIdx.x;
    if (i < n) b[i] = __float2bfloat16_rn(a[i]);
}

// ---------------- LayerNorm (warp per row), bf16 out --------
__global__ void __launch_bounds__(256) ln_kernel(
    const float* __restrict__ in, __nv_bfloat16* __restrict__ out,
    const float* __restrict__ g, const float* __restrict__ b, int gather)
{
    int row  = blockIdx.x * 8 + (threadIdx.x >> 5);
    int lane = threadIdx.x & 31;
    if (row >= MROWS) return;
    int src = gather ? win_to_img(row) : row;

    float4 v = *(const float4*)(in + (size_t)src * CC + lane * 4);
    float s = v.x + v.y + v.z + v.w;
    #pragma unroll
    for (int o = 16; o; o >>= 1) s += __shfl_xor_sync(~0u, s, o);
    float mean = s * (1.f / CC);
    float dx = v.x - mean, dy = v.y - mean, dz = v.z - mean, dw = v.w - mean;
    float vv = dx*dx + dy*dy + dz*dz + dw*dw;
    #pragma unroll
    for (int o = 16; o; o >>= 1) vv += __shfl_xor_sync(~0u, vv, o);
    float rstd = rsqrtf(vv * (1.f / CC) + 1e-5f);

    float4 gg = *(const float4*)(g + lane * 4);
    float4 bb = *(const float4*)(b + lane * 4);
    __nv_bfloat162 p0 = __floats2bfloat162_rn(dx * rstd * gg.x + bb.x, dy * rstd * gg.y + bb.y);
    __nv_bfloat162 p1 = __floats2bfloat162_rn(dz * rstd * gg.z + bb.z, dw * rstd * gg.w + bb.w);
    *(__nv_bfloat162*)(out + (size_t)row * CC + lane * 4)     = p0;
    *(__nv_bfloat162*)(out + (size_t)row * CC + lane * 4 + 2) = p1;
}

// ---------------- HMMA helpers ----------------
__device__ __forceinline__ void ldsm4(uint32_t &r0, uint32_t &r1, uint32_t &r2, uint32_t &r3, uint32_t addr) {
    asm volatile("ldmatrix.sync.aligned.m8n8.x4.shared.b16 {%0,%1,%2,%3}, [%4];\n"
                 : "=r"(r0), "=r"(r1), "=r"(r2), "=r"(r3) : "r"(addr));
}
__device__ __forceinline__ void mma16816(float c[4], uint32_t a0, uint32_t a1, uint32_t a2, uint32_t a3,
                                         uint32_t b0, uint32_t b1) {
    asm volatile("mma.sync.aligned.m16n8k16.row.col.f32.bf16.bf16.f32 "
                 "{%0,%1,%2,%3}, {%4,%5,%6,%7}, {%8,%9}, {%0,%1,%2,%3};\n"
                 : "+f"(c[0]), "+f"(c[1]), "+f"(c[2]), "+f"(c[3])
                 : "r"(a0), "r"(a1), "r"(a2), "r"(a3), "r"(b0), "r"(b1));
}

// ---------------- bf16 tensor-core GEMM: out = A[M,K] @ W[N,K]^T + bias ----
// EPI 0: bf16 out           EPI 1: fp32 scatter+residual
// EPI 2: bf16 exact GELU    EPI 3: fp32 +residual (row layout)
#define LDS_PAD 40   // 32 + 8 bf16 pad

template<int EPI>
__global__ void __launch_bounds__(256) hgemm(
    const __nv_bfloat16* __restrict__ A, const __nv_bfloat16* __restrict__ W,
    const float* __restrict__ bias, void* __restrict__ outp,
    const float* __restrict__ extra, int M, int N, int K)
{
    __shared__ __nv_bfloat16 As[128 * LDS_PAD];
    __shared__ __nv_bfloat16 Bs[128 * LDS_PAD];

    int tid = threadIdx.x, lane = tid & 31, warp = tid >> 5;
    int warp_m = warp & 3, warp_n = warp >> 2;          // 4 x 2 warps
    int blockM = blockIdx.x * 128, blockN = blockIdx.y * 128;

    float acc[2][8][4];
    #pragma unroll
    for (int i = 0; i < 2; i++)
        #pragma unroll
        for (int j = 0; j < 8; j++)
            #pragma unroll
            for (int k = 0; k < 4; k++) acc[i][j][k] = 0.f;

    // ldmatrix lane address pattern
    int grp   = lane >> 3;
    int rowin = (lane & 7) | ((grp & 1) << 3);   // 0..15
    int kin   = (grp >> 1) << 3;                 // 0 or 8

    uint32_t aBase = (uint32_t)__cvta_generic_to_shared(As);
    uint32_t bBase = (uint32_t)__cvta_generic_to_shared(Bs);

    for (int kt = 0; kt < K; kt += 32) {
        // G -> S : each thread moves 2 chunks of 8 bf16 per operand
        #pragma unroll
        for (int c = 0; c < 2; c++) {
            int ch = tid + c * 256;
            int r8 = ch >> 2, k8 = (ch & 3) * 8;
            *(uint4*)&As[r8 * LDS_PAD + k8] =
                *(const uint4*)(A + (size_t)(blockM + r8) * K + kt + k8);
            *(uint4*)&Bs[r8 * LDS_PAD + k8] =
                *(const uint4*)(W + (size_t)(blockN + r8) * K + kt + k8);
        }
        __syncthreads();

        #pragma unroll
        for (int ks = 0; ks < 32; ks += 16) {
            uint32_t af[2][4], bf[4][4];
            #pragma unroll
            for (int mi = 0; mi < 2; mi++) {
                int m = warp_m * 32 + mi * 16 + rowin;
                ldsm4(af[mi][0], af[mi][1], af[mi][2], af[mi][3],
                      aBase + (uint32_t)(m * LDS_PAD + ks + kin) * 2);
            }
            #pragma unroll
            for (int np = 0; np < 4; np++) {
                int n = warp_n * 64 + np * 16 + rowin;
                ldsm4(bf[np][0], bf[np][1], bf[np][2], bf[np][3],
                      bBase + (uint32_t)(n * LDS_PAD + ks + kin) * 2);
            }
            #pragma unroll
            for (int mi = 0; mi < 2; mi++)
                #pragma unroll
                for (int np = 0; np < 4; np++)
                    #pragma unroll
                    for (int sub = 0; sub < 2; sub++)
                        mma16816(acc[mi][np * 2 + sub],
                                 af[mi][0], af[mi][1], af[mi][2], af[mi][3],
                                 bf[np][sub], bf[np][sub + 2]);
        }
        __syncthreads();
    }

    // epilogue
    int rowBase = blockM + warp_m * 32;
    int colBase = blockN + warp_n * 64;
    #pragma unroll
    for (int mi = 0; mi < 2; mi++) {
        #pragma unroll
        for (int h2 = 0; h2 < 2; h2++) {
            int r = rowBase + mi * 16 + (lane >> 2) + h2 * 8;
            size_t orow = (EPI == 1) ? (size_t)win_to_img(r) : (size_t)r;
            #pragma unroll
            for (int ni = 0; ni < 8; ni++) {
                int c = colBase + ni * 8 + (lane & 3) * 2;
                float v0 = acc[mi][ni][h2 * 2 + 0] + bias[c];
                float v1 = acc[mi][ni][h2 * 2 + 1] + bias[c + 1];
                if (EPI == 0) {
                    *(__nv_bfloat162*)((__nv_bfloat16*)outp + (size_t)r * N + c) =
                        __floats2bfloat162_rn(v0, v1);
                } else if (EPI == 1) {
                    float* o = (float*)outp;
                    o[orow * CC + c]     = extra[orow * CC + c]     + v0;
                    o[orow * CC + c + 1] = extra[orow * CC + c + 1] + v1;
                } else if (EPI == 2) {
                    float g0 = 0.5f * v0 * (1.f + erff(v0 * 0.70710678118654752f));
                    float g1 = 0.5f * v1 * (1.f + erff(v1 * 0.70710678118654752f));
                    *(__nv_bfloat162*)((__nv_bfloat16*)outp + (size_t)r * N + c) =
                        __floats2bfloat162_rn(g0, g1);
                } else {
                    float* o = (float*)outp;
                    o[(size_t)r * N + c]     = extra[(size_t)r * N + c]     + v0;
                    o[(size_t)r * N + c + 1] = extra[(size_t)r * N + c + 1] + v1;
                }
            }
        }
    }
}

// ---------------- window attention (register-tiled fp32) ----------------
__global__ void __launch_bounds__(256) attn_kernel(
    const __nv_bfloat16* __restrict__ qkv, const float* __restrict__ rpb,
    __nv_bfloat16* __restrict__ obuf)
{
    int blk = blockIdx.x;
    int w = blk >> 2, h = blk & 3;
    int tid = threadIdx.x;

    __shared__ float qs[52][33], ks[52][33], vs[52][33];
    __shared__ float sc[52][53];
    __shared__ float rpb_s[169];

    const float scale = 0.17677669529663687f;
    size_t base = (size_t)w * NTOK * (3 * CC) + h * HD;

    for (int i = tid; i < NTOK * HD; i += 256) {
        int n = i >> 5, d = i & 31;
        size_t off = base + (size_t)n * (3 * CC) + d;
        qs[n][d] = __bfloat162float(qkv[off]) * scale;
        ks[n][d] = __bfloat162float(qkv[off + CC]);
        vs[n][d] = __bfloat162float(qkv[off + 2 * CC]);
    }
    if (tid < 169) rpb_s[tid] = rpb[tid * NH + h];

    int widx = w & 63;
    int wh = widx >> 3, wwc = widx & 7;
    __syncthreads();

    // scores: 4x4 (n,m) tiles per thread, 13x13 tiles
    if (tid < 169) {
        int tn = tid / 13, tm = tid - tn * 13;
        int n0 = tn * 4, m0 = tm * 4;
        float a[4][4];
        #pragma unroll
        for (int i = 0; i < 4; i++)
            #pragma unroll
            for (int j = 0; j < 4; j++) a[i][j] = 0.f;
        #pragma unroll 8
        for (int d = 0; d < HD; d++) {
            float qv[4], kv[4];
            #pragma unroll
            for (int i = 0; i < 4; i++) qv[i] = qs[n0 + i][d];
            #pragma unroll
            for (int j = 0; j < 4; j++) kv[j] = ks[m0 + j][d];
            #pragma unroll
            for (int i = 0; i < 4; i++)
                #pragma unroll
                for (int j = 0; j < 4; j++) a[i][j] += qv[i] * kv[j];
        }
        #pragma unroll
        for (int i = 0; i < 4; i++) {
            int n = n0 + i;
            int ny = n / WIN, nx = n % WIN;
            int rn = wh * WIN + ny, cn = wwc * WIN + nx;
            int lnr = (rn < 49 ? 0 : (rn < 53 ? 1 : 2)) * 3 + (cn < 49 ? 0 : (cn < 53 ? 1 : 2));
            #pragma unroll
            for (int j = 0; j < 4; j++) {
                int m = m0 + j;
                int my = m / WIN, mx = m % WIN;
                float s = a[i][j] + rpb_s[(ny - my + 6) * 13 + (nx - mx + 6)];
                int rm = wh * WIN + my, cm = wwc * WIN + mx;
                int lmr = (rm < 49 ? 0 : (rm < 53 ? 1 : 2)) * 3 + (cm < 49 ? 0 : (cm < 53 ? 1 : 2));
                if (lnr != lmr) s -= 100.f;
                sc[n][m] = s;
            }
        }
    }
    __syncthreads();

    // softmax: warp per row
    int warp = tid >> 5, lane = tid & 31;
    for (int r = warp; r < NTOK; r += 8) {
        float v0 = sc[r][lane];
        float v1 = (lane < 17) ? sc[r][lane + 32] : -1e30f;
        float mx = fmaxf(v0, v1);
        #pragma unroll
        for (int o = 16; o; o >>= 1) mx = fmaxf(mx, __shfl_xor_sync(~0u, mx, o));
        float e0 = expf(v0 - mx);
        float e1 = (lane < 17) ? expf(v1 - mx) : 0.f;
        float sm = e0 + e1;
        #pragma unroll
        for (int o = 16; o; o >>= 1) sm += __shfl_xor_sync(~0u, sm, o);
        float inv = 1.f / sm;
        sc[r][lane] = e0 * inv;
        if (lane < 17) sc[r][lane + 32] = e1 * inv;
    }
    __syncthreads();

    // PV: 2x4 (n,d) tiles per thread
    if (tid < 200) {
        int tn = tid >> 3, td = tid & 7;
        int n0 = tn * 2, d0 = td * 4;
        float a[2][4];
        #pragma unroll
        for (int i = 0; i < 2; i++)
            #pragma unroll
            for (int j = 0; j < 4; j++) a[i][j] = 0.f;
        for (int m = 0; m < NTOK; m++) {
            float s0 = sc[n0][m], s1 = sc[n0 + 1][m];
            float v0 = vs[m][d0], v1 = vs[m][d0 + 1], v2 = vs[m][d0 + 2], v3 = vs[m][d0 + 3];
            a[0][0] += s0 * v0; a[0][1] += s0 * v1; a[0][2] += s0 * v2; a[0][3] += s0 * v3;
            a[1][0] += s1 * v0; a[1][1] += s1 * v1; a[1][2] += s1 * v2; a[1][3] += s1 * v3;
        }
        #pragma unroll
        for (int i = 0; i < 2; i++) {
            int n = n0 + i;
            if (n < NTOK) {
                size_t off = ((size_t)w * NTOK + n) * CC + h * HD + d0;
                *(__nv_bfloat162*)(obuf + off)     = __floats2bfloat162_rn(a[i][0], a[i][1]);
                *(__nv_bfloat162*)(obuf + off + 2) = __floats2bfloat162_rn(a[i][2], a[i][3]);
            }
        }
    }
}

// ---------------- launch --------------------------------------------------
extern "C" void kernel_launch(void* const* d_in, const int* in_sizes, int n_in,
                              void* d_out, int out_size)
{
    const float* x      = (const float*)d_in[0];
    const float* ln1_g  = (const float*)d_in[1];
    const float* ln1_b  = (const float*)d_in[2];
    const float* qkv_w  = (const float*)d_in[3];
    const float* qkv_b  = (const float*)d_in[4];
    const float* rpb    = (const float*)d_in[5];
    const float* proj_w = (const float*)d_in[6];
    const float* proj_b = (const float*)d_in[7];
    const float* ln2_g  = (const float*)d_in[8];
    const float* ln2_b  = (const float*)d_in[9];
    const float* fc1_w  = (const float*)d_in[10];
    const float* fc1_b  = (const float*)d_in[11];
    const float* fc2_w  = (const float*)d_in[12];
    const float* fc2_b  = (const float*)d_in[13];
    float* out = (float*)d_out;

    __nv_bfloat16 *hwin, *qkvb, *obuf, *act, *wq, *wp, *wf1, *wf2;
    float *x1;
    cudaGetSymbolAddress((void**)&hwin, g_hwin);
    cudaGetSymbolAddress((void**)&qkvb, g_qkv);
    cudaGetSymbolAddress((void**)&obuf, g_obuf);
    cudaGetSymbolAddress((void**)&x1,   g_x1);
    cudaGetSymbolAddress((void**)&act,  g_act);
    cudaGetSymbolAddress((void**)&wq,   g_wq);
    cudaGetSymbolAddress((void**)&wp,   g_wp);
    cudaGetSymbolAddress((void**)&wf1,  g_wf1);
    cudaGetSymbolAddress((void**)&wf2,  g_wf2);

    f2bf_kernel<<<(3*CC*CC + 255) / 256, 256>>>(qkv_w, wq, 3*CC*CC);
    f2bf_kernel<<<(CC*CC + 255) / 256, 256>>>(proj_w, wp, CC*CC);
    f2bf_kernel<<<(MLPH*CC + 255) / 256, 256>>>(fc1_w, wf1, MLPH*CC);
    f2bf_kernel<<<(CC*MLPH + 255) / 256, 256>>>(fc2_w, wf2, CC*MLPH);

    // 1) LN1 + shift + window gather
    ln_kernel<<<MROWS / 8, 256>>>(x, hwin, ln1_g, ln1_b, 1);
    // 2) QKV projection (bf16 out)
    hgemm<0><<<dim3(MROWS / 128, 3), 256>>>(hwin, wq, qkv_b, qkvb, nullptr, MROWS, 3*CC, CC);
    // 3) window attention
    attn_kernel<<<TOTW * NH, 256>>>(qkvb, rpb, obuf);
    // 4) proj + scatter + residual -> x1 fp32
    hgemm<1><<<dim3(MROWS / 128, 1), 256>>>(obuf, wp, proj_b, x1, x, MROWS, CC, CC);
    // 5) LN2
    ln_kernel<<<MROWS / 8, 256>>>(x1, hwin, ln2_g, ln2_b, 0);
    // 6) fc1 + GELU (bf16 out)
    hgemm<2><<<dim3(MROWS / 128, MLPH / 128), 256>>>(hwin, wf1, fc1_b, act, nullptr, MROWS, MLPH, CC);
    // 7) fc2 + residual -> final fp32
    hgemm<3><<<dim3(MROWS / 128, 1), 256>>>(act, wf2, fc2_b, out, x1, MROWS, CC, MLPH);
}

// round 4
// speedup vs baseline: 5.1581x; 1.3013x over previous
#include <cuda_runtime.h>
#include <cuda_bf16.h>
#include <math.h>
#include <stdint.h>

// ---------------- problem constants ----------------
#define BATCH   64
#define HH      56
#define WW_DIM  56
#define CC      128
#define WIN     7
#define SHIFT   3
#define NH      4
#define HD      32
#define NTOK    49
#define TOTW    (BATCH*64)      // 4096 windows
#define MROWS   (TOTW*NTOK)     // 200704 token rows
#define MLPH    512

// ---------------- scratch ----------------
__device__ __nv_bfloat16 g_hwin[(size_t)MROWS*CC];
__device__ __nv_bfloat16 g_qkv [(size_t)MROWS*3*CC];
__device__ __nv_bfloat16 g_obuf[(size_t)MROWS*CC];
__device__ float         g_x1  [(size_t)MROWS*CC];
__device__ __nv_bfloat16 g_act [(size_t)MROWS*MLPH];
__device__ __nv_bfloat16 g_wq [3*CC*CC];
__device__ __nv_bfloat16 g_wp [CC*CC];
__device__ __nv_bfloat16 g_wf1[MLPH*CC];
__device__ __nv_bfloat16 g_wf2[CC*MLPH];

__device__ __forceinline__ int win_to_img(int grow) {
    int w = grow / NTOK, n = grow - w * NTOK;
    int bi = w >> 6, widx = w & 63;
    int r = ((widx >> 3) * WIN + n / WIN + SHIFT) % HH;
    int c = ((widx & 7)  * WIN + n % WIN + SHIFT) % WW_DIM;
    return bi * (HH * WW_DIM) + r * WW_DIM + c;
}

// ---------------- all weights fp32 -> bf16, one launch ----------------
// sizes: 49152 | 16384 | 65536 | 65536  (total 196608 = 768*256)
__global__ void f2bf_all(const float* __restrict__ w0, const float* __restrict__ w1,
                         const float* __restrict__ w2, const float* __restrict__ w3,
                         __nv_bfloat16* o0, __nv_bfloat16* o1,
                         __nv_bfloat16* o2, __nv_bfloat16* o3)
{
    int i = blockIdx.x * 256 + threadIdx.x;
    if (i < 49152)       o0[i]          = __float2bfloat16_rn(w0[i]);
    else if (i < 65536)  o1[i - 49152]  = __float2bfloat16_rn(w1[i - 49152]);
    else if (i < 131072) o2[i - 65536]  = __float2bfloat16_rn(w2[i - 65536]);
    else                 o3[i - 131072] = __float2bfloat16_rn(w3[i - 131072]);
}

// ---------------- LayerNorm (warp per row), bf16 out --------
__global__ void __launch_bounds__(256) ln_kernel(
    const float* __restrict__ in, __nv_bfloat16* __restrict__ out,
    const float* __restrict__ g, const float* __restrict__ b, int gather)
{
    int row  = blockIdx.x * 8 + (threadIdx.x >> 5);
    int lane = threadIdx.x & 31;
    if (row >= MROWS) return;
    int src = gather ? win_to_img(row) : row;

    float4 v = *(const float4*)(in + (size_t)src * CC + lane * 4);
    float s = v.x + v.y + v.z + v.w;
    #pragma unroll
    for (int o = 16; o; o >>= 1) s += __shfl_xor_sync(~0u, s, o);
    float mean = s * (1.f / CC);
    float dx = v.x - mean, dy = v.y - mean, dz = v.z - mean, dw = v.w - mean;
    float vv = dx*dx + dy*dy + dz*dz + dw*dw;
    #pragma unroll
    for (int o = 16; o; o >>= 1) vv += __shfl_xor_sync(~0u, vv, o);
    float rstd = rsqrtf(vv * (1.f / CC) + 1e-5f);

    float4 gg = *(const float4*)(g + lane * 4);
    float4 bb = *(const float4*)(b + lane * 4);
    __nv_bfloat162 p0 = __floats2bfloat162_rn(dx * rstd * gg.x + bb.x, dy * rstd * gg.y + bb.y);
    __nv_bfloat162 p1 = __floats2bfloat162_rn(dz * rstd * gg.z + bb.z, dw * rstd * gg.w + bb.w);
    *(__nv_bfloat162*)(out + (size_t)row * CC + lane * 4)     = p0;
    *(__nv_bfloat162*)(out + (size_t)row * CC + lane * 4 + 2) = p1;
}

// ---------------- HMMA helpers ----------------
__device__ __forceinline__ void ldsm4(uint32_t &r0, uint32_t &r1, uint32_t &r2, uint32_t &r3, uint32_t addr) {
    asm volatile("ldmatrix.sync.aligned.m8n8.x4.shared.b16 {%0,%1,%2,%3}, [%4];\n"
                 : "=r"(r0), "=r"(r1), "=r"(r2), "=r"(r3) : "r"(addr));
}
__device__ __forceinline__ void mma16816(float c[4], uint32_t a0, uint32_t a1, uint32_t a2, uint32_t a3,
                                         uint32_t b0, uint32_t b1) {
    asm volatile("mma.sync.aligned.m16n8k16.row.col.f32.bf16.bf16.f32 "
                 "{%0,%1,%2,%3}, {%4,%5,%6,%7}, {%8,%9}, {%0,%1,%2,%3};\n"
                 : "+f"(c[0]), "+f"(c[1]), "+f"(c[2]), "+f"(c[3])
                 : "r"(a0), "r"(a1), "r"(a2), "r"(a3), "r"(b0), "r"(b1));
}
__device__ __forceinline__ uint32_t pack_bf2(float a, float b) {
    __nv_bfloat162 p = __floats2bfloat162_rn(a, b);
    return *(uint32_t*)&p;
}

// ---------------- bf16 tensor-core GEMM: out = A[M,K] @ W[N,K]^T + bias ----
// k-chunk = 64, smem stride 72
#define KC     64
#define SPITCH 72

template<int EPI>
__global__ void __launch_bounds__(256) hgemm(
    const __nv_bfloat16* __restrict__ A, const __nv_bfloat16* __restrict__ W,
    const float* __restrict__ bias, void* __restrict__ outp,
    const float* __restrict__ extra, int M, int N, int K)
{
    __shared__ __align__(16) __nv_bfloat16 As[128 * SPITCH];
    __shared__ __align__(16) __nv_bfloat16 Bs[128 * SPITCH];

    int tid = threadIdx.x, lane = tid & 31, warp = tid >> 5;
    int warp_m = warp & 3, warp_n = warp >> 2;          // 4 x 2 warps
    int blockM = blockIdx.x * 128, blockN = blockIdx.y * 128;

    float acc[2][8][4];
    #pragma unroll
    for (int i = 0; i < 2; i++)
        #pragma unroll
        for (int j = 0; j < 8; j++)
            #pragma unroll
            for (int k = 0; k < 4; k++) acc[i][j][k] = 0.f;

    int grp   = lane >> 3;
    int rowin = (lane & 7) | ((grp & 1) << 3);
    int kin   = (grp >> 1) << 3;

    uint32_t aBase = (uint32_t)__cvta_generic_to_shared(As);
    uint32_t bBase = (uint32_t)__cvta_generic_to_shared(Bs);

    for (int kt = 0; kt < K; kt += KC) {
        // G -> S : 128 rows x 64 cols per operand, 4 uint4 per thread each
        #pragma unroll
        for (int c = 0; c < 4; c++) {
            int ch = c * 256 + tid;
            int r8 = ch >> 3, k8 = (ch & 7) * 8;
            *(uint4*)&As[r8 * SPITCH + k8] =
                *(const uint4*)(A + (size_t)(blockM + r8) * K + kt + k8);
            *(uint4*)&Bs[r8 * SPITCH + k8] =
                *(const uint4*)(W + (size_t)(blockN + r8) * K + kt + k8);
        }
        __syncthreads();

        #pragma unroll
        for (int ks = 0; ks < KC; ks += 16) {
            uint32_t af[2][4], bfr[4][4];
            #pragma unroll
            for (int mi = 0; mi < 2; mi++) {
                int m = warp_m * 32 + mi * 16 + rowin;
                ldsm4(af[mi][0], af[mi][1], af[mi][2], af[mi][3],
                      aBase + (uint32_t)(m * SPITCH + ks + kin) * 2);
            }
            #pragma unroll
            for (int np = 0; np < 4; np++) {
                int n = warp_n * 64 + np * 16 + rowin;
                ldsm4(bfr[np][0], bfr[np][1], bfr[np][2], bfr[np][3],
                      bBase + (uint32_t)(n * SPITCH + ks + kin) * 2);
            }
            #pragma unroll
            for (int mi = 0; mi < 2; mi++)
                #pragma unroll
                for (int np = 0; np < 4; np++)
                    #pragma unroll
                    for (int sub = 0; sub < 2; sub++)
                        mma16816(acc[mi][np * 2 + sub],
                                 af[mi][0], af[mi][1], af[mi][2], af[mi][3],
                                 bfr[np][sub], bfr[np][sub + 2]);
        }
        __syncthreads();
    }

    // epilogue
    int rowBase = blockM + warp_m * 32;
    int colBase = blockN + warp_n * 64;
    #pragma unroll
    for (int mi = 0; mi < 2; mi++) {
        #pragma unroll
        for (int h2 = 0; h2 < 2; h2++) {
            int r = rowBase + mi * 16 + (lane >> 2) + h2 * 8;
            size_t orow = (EPI == 1) ? (size_t)win_to_img(r) : (size_t)r;
            #pragma unroll
            for (int ni = 0; ni < 8; ni++) {
                int c = colBase + ni * 8 + (lane & 3) * 2;
                float v0 = acc[mi][ni][h2 * 2 + 0] + bias[c];
                float v1 = acc[mi][ni][h2 * 2 + 1] + bias[c + 1];
                if (EPI == 0) {
                    *(__nv_bfloat162*)((__nv_bfloat16*)outp + (size_t)r * N + c) =
                        __floats2bfloat162_rn(v0, v1);
                } else if (EPI == 1) {
                    float* o = (float*)outp;
                    o[orow * CC + c]     = extra[orow * CC + c]     + v0;
                    o[orow * CC + c + 1] = extra[orow * CC + c + 1] + v1;
                } else if (EPI == 2) {
                    float g0 = 0.5f * v0 * (1.f + erff(v0 * 0.70710678118654752f));
                    float g1 = 0.5f * v1 * (1.f + erff(v1 * 0.70710678118654752f));
                    *(__nv_bfloat162*)((__nv_bfloat16*)outp + (size_t)r * N + c) =
                        __floats2bfloat162_rn(g0, g1);
                } else {
                    float* o = (float*)outp;
                    o[(size_t)r * N + c]     = extra[(size_t)r * N + c]     + v0;
                    o[(size_t)r * N + c + 1] = extra[(size_t)r * N + c + 1] + v1;
                }
            }
        }
    }
}

// ---------------- tensor-core window attention --------------------------
// one 128-thread block per (window, head); tokens padded 49 -> 64
__global__ void __launch_bounds__(128) attn_tc(
    const __nv_bfloat16* __restrict__ qkv, const float* __restrict__ rpb,
    __nv_bfloat16* __restrict__ obuf)
{
    int w = blockIdx.x >> 2, h = blockIdx.x & 3;
    int tid = threadIdx.x, lane = tid & 31, warp = tid >> 5;

    __shared__ __align__(16) __nv_bfloat16 qs[64 * 40];
    __shared__ __align__(16) __nv_bfloat16 kts[64 * 40];
    __shared__ __align__(16) __nv_bfloat16 vs[32 * 72];   // [d][tok]
    __shared__ float rpb_s[169];
    __shared__ int pn[64], lab[64];

    const float scale = 0.17677669529663687f;
    size_t base = (size_t)w * NTOK * (3 * CC) + h * HD;

    for (int i = tid; i < 2048; i += 128) {
        int n = i >> 5, d = i & 31;
        __nv_bfloat16 qv, kv, vv;
        if (n < NTOK) {
            size_t off = base + (size_t)n * (3 * CC) + d;
            qv = __float2bfloat16_rn(__bfloat162float(qkv[off]) * scale);
            kv = qkv[off + CC];
            vv = qkv[off + 2 * CC];
        } else {
            qv = kv = vv = __float2bfloat16_rn(0.f);
        }
        qs [n * 40 + d] = qv;
        kts[n * 40 + d] = kv;
        vs [d * 72 + n] = vv;
    }
    for (int i = tid; i < 169; i += 128) rpb_s[i] = rpb[i * NH + h];
    {
        int widx = w & 63;
        int wh = widx >> 3, wwc = widx & 7;
        if (tid < 64) {
            int n = tid;
            if (n < NTOK) {
                int ny = n / 7, nx = n % 7;
                pn[n] = ny * 13 + nx;
                int rn = wh * 7 + ny, cn = wwc * 7 + nx;
                lab[n] = (rn < 49 ? 0 : (rn < 53 ? 1 : 2)) * 3 +
                         (cn < 49 ? 0 : (cn < 53 ? 1 : 2));
            } else { pn[n] = 0; lab[n] = -1; }
        }
    }
    __syncthreads();

    int grp   = lane >> 3;
    int rowin = (lane & 7) | ((grp & 1) << 3);
    int kin   = (grp >> 1) << 3;
    uint32_t qB = (uint32_t)__cvta_generic_to_shared(qs);
    uint32_t kB = (uint32_t)__cvta_generic_to_shared(kts);
    uint32_t vB = (uint32_t)__cvta_generic_to_shared(vs);

    // ---- scores: S[64x64] = Q @ K^T, warp owns 16 rows ----
    float acc[8][4];
    #pragma unroll
    for (int i = 0; i < 8; i++)
        #pragma unroll
        for (int j = 0; j < 4; j++) acc[i][j] = 0.f;

    int r0 = warp * 16;
    #pragma unroll
    for (int ks = 0; ks < 32; ks += 16) {
        uint32_t af[4];
        ldsm4(af[0], af[1], af[2], af[3],
              qB + (uint32_t)((r0 + rowin) * 40 + ks + kin) * 2);
        #pragma unroll
        for (int np = 0; np < 4; np++) {
            uint32_t bv[4];
            ldsm4(bv[0], bv[1], bv[2], bv[3],
                  kB + (uint32_t)((np * 16 + rowin) * 40 + ks + kin) * 2);
            mma16816(acc[np * 2 + 0], af[0], af[1], af[2], af[3], bv[0], bv[2]);
            mma16816(acc[np * 2 + 1], af[0], af[1], af[2], af[3], bv[1], bv[3]);
        }
    }

    // ---- bias + mask on fragments ----
    int rA = r0 + (lane >> 2), rB = rA + 8;
    int pA = pn[rA], pB = pn[rB];
    int lA = lab[rA], lB = lab[rB];
    #pragma unroll
    for (int nt = 0; nt < 8; nt++) {
        int m0 = nt * 8 + (lane & 3) * 2;
        #pragma unroll
        for (int dmi = 0; dmi < 2; dmi++) {
            int m = m0 + dmi;
            if (m < NTOK) {
                int pm = pn[m], lm = lab[m];
                float bA = rpb_s[pA - pm + 84] + (lA != lm ? -100.f : 0.f);
                float bB = rpb_s[pB - pm + 84] + (lB != lm ? -100.f : 0.f);
                acc[nt][dmi]     += bA;
                acc[nt][dmi + 2] += bB;
            } else {
                acc[nt][dmi]     = -1e30f;
                acc[nt][dmi + 2] = -1e30f;
            }
        }
    }

    // ---- softmax over rows (rA and rB), quad reduction ----
    float mA = -1e30f, mB = -1e30f;
    #pragma unroll
    for (int nt = 0; nt < 8; nt++) {
        mA = fmaxf(mA, fmaxf(acc[nt][0], acc[nt][1]));
        mB = fmaxf(mB, fmaxf(acc[nt][2], acc[nt][3]));
    }
    mA = fmaxf(mA, __shfl_xor_sync(~0u, mA, 1));
    mA = fmaxf(mA, __shfl_xor_sync(~0u, mA, 2));
    mB = fmaxf(mB, __shfl_xor_sync(~0u, mB, 1));
    mB = fmaxf(mB, __shfl_xor_sync(~0u, mB, 2));
    float sA = 0.f, sB = 0.f;
    #pragma unroll
    for (int nt = 0; nt < 8; nt++) {
        acc[nt][0] = __expf(acc[nt][0] - mA);
        acc[nt][1] = __expf(acc[nt][1] - mA);
        acc[nt][2] = __expf(acc[nt][2] - mB);
        acc[nt][3] = __expf(acc[nt][3] - mB);
        sA += acc[nt][0] + acc[nt][1];
        sB += acc[nt][2] + acc[nt][3];
    }
    sA += __shfl_xor_sync(~0u, sA, 1);
    sA += __shfl_xor_sync(~0u, sA, 2);
    sB += __shfl_xor_sync(~0u, sB, 1);
    sB += __shfl_xor_sync(~0u, sB, 2);
    float invA = 1.f / sA, invB = 1.f / sB;

    // ---- pack P fragments (C-layout -> A-layout, in registers) ----
    uint32_t pa[4][4];
    #pragma unroll
    for (int j = 0; j < 4; j++) {
        pa[j][0] = pack_bf2(acc[2*j][0]   * invA, acc[2*j][1]   * invA);
        pa[j][1] = pack_bf2(acc[2*j][2]   * invB, acc[2*j][3]   * invB);
        pa[j][2] = pack_bf2(acc[2*j+1][0] * invA, acc[2*j+1][1] * invA);
        pa[j][3] = pack_bf2(acc[2*j+1][2] * invB, acc[2*j+1][3] * invB);
    }

    // ---- O = P @ V : K=64 (tokens), N=32 (head dim) ----
    float oacc[4][4];
    #pragma unroll
    for (int i = 0; i < 4; i++)
        #pragma unroll
        for (int j = 0; j < 4; j++) oacc[i][j] = 0.f;

    #pragma unroll
    for (int j = 0; j < 4; j++) {
        #pragma unroll
        for (int dg = 0; dg < 2; dg++) {
            uint32_t bv[4];
            ldsm4(bv[0], bv[1], bv[2], bv[3],
                  vB + (uint32_t)((dg * 16 + rowin) * 72 + j * 16 + kin) * 2);
            mma16816(oacc[dg * 2 + 0], pa[j][0], pa[j][1], pa[j][2], pa[j][3], bv[0], bv[2]);
            mma16816(oacc[dg * 2 + 1], pa[j][0], pa[j][1], pa[j][2], pa[j][3], bv[1], bv[3]);
        }
    }

    // ---- write O (rows < 49) ----
    #pragma unroll
    for (int nd = 0; nd < 4; nd++) {
        int c = h * HD + nd * 8 + (lane & 3) * 2;
        if (rA < NTOK)
            *(__nv_bfloat162*)(obuf + ((size_t)w * NTOK + rA) * CC + c) =
                __floats2bfloat162_rn(oacc[nd][0], oacc[nd][1]);
        if (rB < NTOK)
            *(__nv_bfloat162*)(obuf + ((size_t)w * NTOK + rB) * CC + c) =
                __floats2bfloat162_rn(oacc[nd][2], oacc[nd][3]);
    }
}

// ---------------- launch --------------------------------------------------
extern "C" void kernel_launch(void* const* d_in, const int* in_sizes, int n_in,
                              void* d_out, int out_size)
{
    const float* x      = (const float*)d_in[0];
    const float* ln1_g  = (const float*)d_in[1];
    const float* ln1_b  = (const float*)d_in[2];
    const float* qkv_w  = (const float*)d_in[3];
    const float* qkv_b  = (const float*)d_in[4];
    const float* rpb    = (const float*)d_in[5];
    const float* proj_w = (const float*)d_in[6];
    const float* proj_b = (const float*)d_in[7];
    const float* ln2_g  = (const float*)d_in[8];
    const float* ln2_b  = (const float*)d_in[9];
    const float* fc1_w  = (const float*)d_in[10];
    const float* fc1_b  = (const float*)d_in[11];
    const float* fc2_w  = (const float*)d_in[12];
    const float* fc2_b  = (const float*)d_in[13];
    float* out = (float*)d_out;

    __nv_bfloat16 *hwin, *qkvb, *obuf, *act, *wq, *wp, *wf1, *wf2;
    float *x1;
    cudaGetSymbolAddress((void**)&hwin, g_hwin);
    cudaGetSymbolAddress((void**)&qkvb, g_qkv);
    cudaGetSymbolAddress((void**)&obuf, g_obuf);
    cudaGetSymbolAddress((void**)&x1,   g_x1);
    cudaGetSymbolAddress((void**)&act,  g_act);
    cudaGetSymbolAddress((void**)&wq,   g_wq);
    cudaGetSymbolAddress((void**)&wp,   g_wp);
    cudaGetSymbolAddress((void**)&wf1,  g_wf1);
    cudaGetSymbolAddress((void**)&wf2,  g_wf2);

    // 0) all weight conversions in one launch
    f2bf_all<<<768, 256>>>(qkv_w, proj_w, fc1_w, fc2_w, wq, wp, wf1, wf2);

    // 1) LN1 + shift + window gather
    ln_kernel<<<MROWS / 8, 256>>>(x, hwin, ln1_g, ln1_b, 1);
    // 2) QKV projection (bf16 out)
    hgemm<0><<<dim3(MROWS / 128, 3), 256>>>(hwin, wq, qkv_b, qkvb, nullptr, MROWS, 3*CC, CC);
    // 3) tensor-core window attention
    attn_tc<<<TOTW * NH, 128>>>(qkvb, rpb, obuf);
    // 4) proj + scatter + residual -> x1 fp32
    hgemm<1><<<dim3(MROWS / 128, 1), 256>>>(obuf, wp, proj_b, x1, x, MROWS, CC, CC);
    // 5) LN2
    ln_kernel<<<MROWS / 8, 256>>>(x1, hwin, ln2_g, ln2_b, 0);
    // 6) fc1 + GELU (bf16 out)
    hgemm<2><<<dim3(MROWS / 128, MLPH / 128), 256>>>(hwin, wf1, fc1_b, act, nullptr, MROWS, MLPH, CC);
    // 7) fc2 + residual -> final fp32
    hgemm<3><<<dim3(MROWS / 128, 1), 256>>>(act, wf2, fc2_b, out, x1, MROWS, CC, MLPH);
}

// round 5
// speedup vs baseline: 5.7731x; 1.1192x over previous
#include <cuda_runtime.h>
#include <cuda_bf16.h>
#include <math.h>
#include <stdint.h>

// ---------------- problem constants ----------------
#define BATCH   64
#define HH      56
#define WW_DIM  56
#define CC      128
#define WIN     7
#define SHIFT   3
#define NH      4
#define HD      32
#define NTOK    49
#define TOTW    (BATCH*64)      // 4096 windows
#define MROWS   (TOTW*NTOK)     // 200704 token rows
#define MLPH    512

// ---------------- scratch ----------------
__device__ __nv_bfloat16 g_hwin[(size_t)MROWS*CC];
__device__ __nv_bfloat16 g_qkv [(size_t)MROWS*3*CC];
__device__ __nv_bfloat16 g_obuf[(size_t)MROWS*CC];
__device__ float         g_x1  [(size_t)MROWS*CC];
__device__ __nv_bfloat16 g_act [(size_t)MROWS*MLPH];
__device__ __nv_bfloat16 g_wq [3*CC*CC];
__device__ __nv_bfloat16 g_wp [CC*CC];
__device__ __nv_bfloat16 g_wf1[MLPH*CC];
__device__ __nv_bfloat16 g_wf2[CC*MLPH];
__device__ float g_bq[3*CC];          // scaled qkv bias
__device__ float g_bm[4*4*64*64];     // fused bias+mask table

__device__ __forceinline__ int win_to_img(int grow) {
    int w = grow / NTOK, n = grow - w * NTOK;
    int bi = w >> 6, widx = w & 63;
    int r = ((widx >> 3) * WIN + n / WIN + SHIFT) % HH;
    int c = ((widx & 7)  * WIN + n % WIN + SHIFT) % WW_DIM;
    return bi * (HH * WW_DIM) + r * WW_DIM + c;
}

#define QSCALE 0.17677669529663687f

// ---------------- weights fp32 -> bf16 (+ fold q scale), one launch --------
__global__ void f2bf_all(const float* __restrict__ w0, const float* __restrict__ w1,
                         const float* __restrict__ w2, const float* __restrict__ w3,
                         const float* __restrict__ qb,
                         __nv_bfloat16* o0, __nv_bfloat16* o1,
                         __nv_bfloat16* o2, __nv_bfloat16* o3, float* bq)
{
    int i = blockIdx.x * 256 + threadIdx.x;
    if (i < 49152) {
        float v = w0[i];
        if (i < 16384) v *= QSCALE;     // rows 0..127 = Q weights
        o0[i] = __float2bfloat16_rn(v);
    }
    else if (i < 65536)  o1[i - 49152]  = __float2bfloat16_rn(w1[i - 49152]);
    else if (i < 131072) o2[i - 65536]  = __float2bfloat16_rn(w2[i - 65536]);
    else                 o3[i - 131072] = __float2bfloat16_rn(w3[i - 131072]);
    if (i < 384) bq[i] = qb[i] * (i < 128 ? QSCALE : 1.f);
}

// ---------------- fused relative-pos-bias + shift-mask table ---------------
// bm[wt][h][n][m] ; wt = (wh==7)*2 + (ww==7) ; padded cols m>=49 -> -1e30
__global__ void bm_init(const float* __restrict__ rpb, float* __restrict__ bm)
{
    int idx = blockIdx.x * 256 + threadIdx.x;   // 65536
    int m = idx & 63, n = (idx >> 6) & 63, h = (idx >> 12) & 3, wt = idx >> 14;
    float v;
    if (m >= NTOK) v = -1e30f;
    else {
        int ne = n < NTOK ? n : NTOK - 1;
        int ny = ne / 7, nx = ne % 7, my = m / 7, mx = m % 7;
        v = rpb[((ny - my + 6) * 13 + (nx - mx + 6)) * NH + h];
        int wh7 = wt >> 1, ww7 = wt & 1;
        int lrn = wh7 ? (ny < 4 ? 1 : 2) : 0;
        int lcn = ww7 ? (nx < 4 ? 1 : 2) : 0;
        int lrm = wh7 ? (my < 4 ? 1 : 2) : 0;
        int lcm = ww7 ? (mx < 4 ? 1 : 2) : 0;
        if (lrn * 3 + lcn != lrm * 3 + lcm) v -= 100.f;
    }
    bm[idx] = v;
}

// ---------------- LayerNorm (warp per row), bf16 out --------
__global__ void __launch_bounds__(256) ln_kernel(
    const float* __restrict__ in, __nv_bfloat16* __restrict__ out,
    const float* __restrict__ g, const float* __restrict__ b, int gather)
{
    int row  = blockIdx.x * 8 + (threadIdx.x >> 5);
    int lane = threadIdx.x & 31;
    if (row >= MROWS) return;
    int src = gather ? win_to_img(row) : row;

    float4 v = *(const float4*)(in + (size_t)src * CC + lane * 4);
    float s = v.x + v.y + v.z + v.w;
    #pragma unroll
    for (int o = 16; o; o >>= 1) s += __shfl_xor_sync(~0u, s, o);
    float mean = s * (1.f / CC);
    float dx = v.x - mean, dy = v.y - mean, dz = v.z - mean, dw = v.w - mean;
    float vv = dx*dx + dy*dy + dz*dz + dw*dw;
    #pragma unroll
    for (int o = 16; o; o >>= 1) vv += __shfl_xor_sync(~0u, vv, o);
    float rstd = rsqrtf(vv * (1.f / CC) + 1e-5f);

    float4 gg = *(const float4*)(g + lane * 4);
    float4 bb = *(const float4*)(b + lane * 4);
    __nv_bfloat162 p0 = __floats2bfloat162_rn(dx * rstd * gg.x + bb.x, dy * rstd * gg.y + bb.y);
    __nv_bfloat162 p1 = __floats2bfloat162_rn(dz * rstd * gg.z + bb.z, dw * rstd * gg.w + bb.w);
    *(__nv_bfloat162*)(out + (size_t)row * CC + lane * 4)     = p0;
    *(__nv_bfloat162*)(out + (size_t)row * CC + lane * 4 + 2) = p1;
}

// ---------------- HMMA / cp.async helpers ----------------
__device__ __forceinline__ void ldsm4(uint32_t &r0, uint32_t &r1, uint32_t &r2, uint32_t &r3, uint32_t addr) {
    asm volatile("ldmatrix.sync.aligned.m8n8.x4.shared.b16 {%0,%1,%2,%3}, [%4];\n"
                 : "=r"(r0), "=r"(r1), "=r"(r2), "=r"(r3) : "r"(addr));
}
__device__ __forceinline__ void ldsm4t(uint32_t &r0, uint32_t &r1, uint32_t &r2, uint32_t &r3, uint32_t addr) {
    asm volatile("ldmatrix.sync.aligned.m8n8.x4.trans.shared.b16 {%0,%1,%2,%3}, [%4];\n"
                 : "=r"(r0), "=r"(r1), "=r"(r2), "=r"(r3) : "r"(addr));
}
__device__ __forceinline__ void mma16816(float c[4], uint32_t a0, uint32_t a1, uint32_t a2, uint32_t a3,
                                         uint32_t b0, uint32_t b1) {
    asm volatile("mma.sync.aligned.m16n8k16.row.col.f32.bf16.bf16.f32 "
                 "{%0,%1,%2,%3}, {%4,%5,%6,%7}, {%8,%9}, {%0,%1,%2,%3};\n"
                 : "+f"(c[0]), "+f"(c[1]), "+f"(c[2]), "+f"(c[3])
                 : "r"(a0), "r"(a1), "r"(a2), "r"(a3), "r"(b0), "r"(b1));
}
__device__ __forceinline__ uint32_t pack_bf2(float a, float b) {
    __nv_bfloat162 p = __floats2bfloat162_rn(a, b);
    return *(uint32_t*)&p;
}
__device__ __forceinline__ void cp16(uint32_t dst, const void* src) {
    asm volatile("cp.async.ca.shared.global [%0], [%1], 16;\n" :: "r"(dst), "l"(src));
}

// ---------------- bf16 TC GEMM, cp.async 2-stage: out = A @ W^T + bias -----
#define KC     32
#define SPITCH 40
#define STAGEB (128 * SPITCH * 2)    // bytes per operand stage

template<int EPI>
__global__ void __launch_bounds__(256) hgemm(
    const __nv_bfloat16* __restrict__ A, const __nv_bfloat16* __restrict__ W,
    const float* __restrict__ bias, void* __restrict__ outp,
    const float* __restrict__ extra, int M, int N, int K)
{
    __shared__ __align__(16) __nv_bfloat16 As[2][128 * SPITCH];
    __shared__ __align__(16) __nv_bfloat16 Bs[2][128 * SPITCH];

    int tid = threadIdx.x, lane = tid & 31, warp = tid >> 5;
    int warp_m = warp & 3, warp_n = warp >> 2;          // 4 x 2 warps
    int blockM = blockIdx.x * 128, blockN = blockIdx.y * 128;

    float acc[2][8][4];
    #pragma unroll
    for (int i = 0; i < 2; i++)
        #pragma unroll
        for (int j = 0; j < 8; j++)
            #pragma unroll
            for (int k = 0; k < 4; k++) acc[i][j][k] = 0.f;

    int grp   = lane >> 3;
    int rowin = (lane & 7) | ((grp & 1) << 3);
    int kin   = (grp >> 1) << 3;

    uint32_t aBase = (uint32_t)__cvta_generic_to_shared(&As[0][0]);
    uint32_t bBase = (uint32_t)__cvta_generic_to_shared(&Bs[0][0]);

    int r8 = tid >> 2, k8 = (tid & 3) * 8;       // chunk 0
    int r8b = (tid + 256) >> 2, k8b = ((tid + 256) & 3) * 8;

    // prologue: stage 0
    {
        cp16(aBase + (r8  * SPITCH + k8 ) * 2, A + (size_t)(blockM + r8 ) * K + k8 );
        cp16(aBase + (r8b * SPITCH + k8b) * 2, A + (size_t)(blockM + r8b) * K + k8b);
        cp16(bBase + (r8  * SPITCH + k8 ) * 2, W + (size_t)(blockN + r8 ) * K + k8 );
        cp16(bBase + (r8b * SPITCH + k8b) * 2, W + (size_t)(blockN + r8b) * K + k8b);
        asm volatile("cp.async.commit_group;\n");
    }

    int nk = K >> 5;
    for (int s = 0; s < nk; s++) {
        if (s + 1 < nk) {
            int kt = (s + 1) << 5;
            uint32_t ao = aBase + ((s + 1) & 1) * STAGEB;
            uint32_t bo = bBase + ((s + 1) & 1) * STAGEB;
            cp16(ao + (r8  * SPITCH + k8 ) * 2, A + (size_t)(blockM + r8 ) * K + kt + k8 );
            cp16(ao + (r8b * SPITCH + k8b) * 2, A + (size_t)(blockM + r8b) * K + kt + k8b);
            cp16(bo + (r8  * SPITCH + k8 ) * 2, W + (size_t)(blockN + r8 ) * K + kt + k8 );
            cp16(bo + (r8b * SPITCH + k8b) * 2, W + (size_t)(blockN + r8b) * K + kt + k8b);
            asm volatile("cp.async.commit_group;\n");
            asm volatile("cp.async.wait_group 1;\n");
        } else {
            asm volatile("cp.async.wait_group 0;\n");
        }
        __syncthreads();

        uint32_t aS = aBase + (s & 1) * STAGEB;
        uint32_t bS = bBase + (s & 1) * STAGEB;
        #pragma unroll
        for (int ks = 0; ks < KC; ks += 16) {
            uint32_t af[2][4], bfr[4][4];
            #pragma unroll
            for (int mi = 0; mi < 2; mi++) {
                int m = warp_m * 32 + mi * 16 + rowin;
                ldsm4(af[mi][0], af[mi][1], af[mi][2], af[mi][3],
                      aS + (uint32_t)(m * SPITCH + ks + kin) * 2);
            }
            #pragma unroll
            for (int np = 0; np < 4; np++) {
                int n = warp_n * 64 + np * 16 + rowin;
                ldsm4(bfr[np][0], bfr[np][1], bfr[np][2], bfr[np][3],
                      bS + (uint32_t)(n * SPITCH + ks + kin) * 2);
            }
            #pragma unroll
            for (int mi = 0; mi < 2; mi++)
                #pragma unroll
                for (int np = 0; np < 4; np++)
                    #pragma unroll
                    for (int sub = 0; sub < 2; sub++)
                        mma16816(acc[mi][np * 2 + sub],
                                 af[mi][0], af[mi][1], af[mi][2], af[mi][3],
                                 bfr[np][sub], bfr[np][sub + 2]);
        }
        __syncthreads();
    }

    // epilogue
    int rowBase = blockM + warp_m * 32;
    int colBase = blockN + warp_n * 64;
    #pragma unroll
    for (int mi = 0; mi < 2; mi++) {
        #pragma unroll
        for (int h2 = 0; h2 < 2; h2++) {
            int r = rowBase + mi * 16 + (lane >> 2) + h2 * 8;
            size_t orow = (EPI == 1) ? (size_t)win_to_img(r) : (size_t)r;
            #pragma unroll
            for (int ni = 0; ni < 8; ni++) {
                int c = colBase + ni * 8 + (lane & 3) * 2;
                float v0 = acc[mi][ni][h2 * 2 + 0] + bias[c];
                float v1 = acc[mi][ni][h2 * 2 + 1] + bias[c + 1];
                if (EPI == 0) {
                    *(__nv_bfloat162*)((__nv_bfloat16*)outp + (size_t)r * N + c) =
                        __floats2bfloat162_rn(v0, v1);
                } else if (EPI == 1) {
                    float* o = (float*)outp;
                    o[orow * CC + c]     = extra[orow * CC + c]     + v0;
                    o[orow * CC + c + 1] = extra[orow * CC + c + 1] + v1;
                } else if (EPI == 2) {
                    float g0 = 0.5f * v0 * (1.f + erff(v0 * 0.70710678118654752f));
                    float g1 = 0.5f * v1 * (1.f + erff(v1 * 0.70710678118654752f));
                    *(__nv_bfloat162*)((__nv_bfloat16*)outp + (size_t)r * N + c) =
                        __floats2bfloat162_rn(g0, g1);
                } else {
                    float* o = (float*)outp;
                    o[(size_t)r * N + c]     = extra[(size_t)r * N + c]     + v0;
                    o[(size_t)r * N + c + 1] = extra[(size_t)r * N + c + 1] + v1;
                }
            }
        }
    }
}

// ---------------- tensor-core window attention --------------------------
// one 128-thread block per (window, head); tokens padded 49 -> 64
__global__ void __launch_bounds__(128) attn_tc(
    const __nv_bfloat16* __restrict__ qkv, const float* __restrict__ bm,
    __nv_bfloat16* __restrict__ obuf)
{
    int w = blockIdx.x >> 2, h = blockIdx.x & 3;
    int tid = threadIdx.x, lane = tid & 31, warp = tid >> 5;

    __shared__ __align__(16) __nv_bfloat16 qs[64 * 40];
    __shared__ __align__(16) __nv_bfloat16 ks[64 * 40];
    __shared__ __align__(16) __nv_bfloat16 vsn[64 * 40];   // [tok][d]

    size_t base = (size_t)w * NTOK * (3 * CC) + h * HD;

    // vectorized staging: 64 rows x 4 uint4-chunks, zeros in pad rows
    #pragma unroll
    for (int i = tid; i < 256; i += 128) {
        int n = i >> 2, j = i & 3;
        uint4 qv = {0,0,0,0}, kv = {0,0,0,0}, vv = {0,0,0,0};
        if (n < NTOK) {
            const __nv_bfloat16* src = qkv + base + (size_t)n * (3 * CC) + j * 8;
            qv = *(const uint4*)(src);
            kv = *(const uint4*)(src + CC);
            vv = *(const uint4*)(src + 2 * CC);
        }
        *(uint4*)&qs [n * 40 + j * 8] = qv;
        *(uint4*)&ks [n * 40 + j * 8] = kv;
        *(uint4*)&vsn[n * 40 + j * 8] = vv;
    }
    __syncthreads();

    int grp   = lane >> 3;
    int rowin = (lane & 7) | ((grp & 1) << 3);
    int kin   = (grp >> 1) << 3;
    uint32_t qB = (uint32_t)__cvta_generic_to_shared(qs);
    uint32_t kB = (uint32_t)__cvta_generic_to_shared(ks);
    uint32_t vB = (uint32_t)__cvta_generic_to_shared(vsn);

    // ---- scores: S[64x64] = Q @ K^T, warp owns 16 rows ----
    float acc[8][4];
    #pragma unroll
    for (int i = 0; i < 8; i++)
        #pragma unroll
        for (int j = 0; j < 4; j++) acc[i][j] = 0.f;

    int r0 = warp * 16;
    #pragma unroll
    for (int kk = 0; kk < 32; kk += 16) {
        uint32_t af[4];
        ldsm4(af[0], af[1], af[2], af[3],
              qB + (uint32_t)((r0 + rowin) * 40 + kk + kin) * 2);
        #pragma unroll
        for (int np = 0; np < 4; np++) {
            uint32_t bv[4];
            ldsm4(bv[0], bv[1], bv[2], bv[3],
                  kB + (uint32_t)((np * 16 + rowin) * 40 + kk + kin) * 2);
            mma16816(acc[np * 2 + 0], af[0], af[1], af[2], af[3], bv[0], bv[2]);
            mma16816(acc[np * 2 + 1], af[0], af[1], af[2], af[3], bv[1], bv[3]);
        }
    }

    // ---- fused bias+mask from precomputed table ----
    int rA = r0 + (lane >> 2);
    int widx = w & 63;
    int wt = (((widx >> 3) == 7) ? 2 : 0) | (((widx & 7) == 7) ? 1 : 0);
    const float* bmA = bm + (((wt << 2) | h) << 12) + rA * 64;
    const float* bmB = bmA + 8 * 64;
    int mcol = (lane & 3) * 2;
    #pragma unroll
    for (int nt = 0; nt < 8; nt++) {
        float2 bA = *(const float2*)(bmA + nt * 8 + mcol);
        float2 bB = *(const float2*)(bmB + nt * 8 + mcol);
        acc[nt][0] += bA.x; acc[nt][1] += bA.y;
        acc[nt][2] += bB.x; acc[nt][3] += bB.y;
    }

    // ---- softmax over rows (rA and rA+8), quad reduction ----
    float mA = -1e30f, mB = -1e30f;
    #pragma unroll
    for (int nt = 0; nt < 8; nt++) {
        mA = fmaxf(mA, fmaxf(acc[nt][0], acc[nt][1]));
        mB = fmaxf(mB, fmaxf(acc[nt][2], acc[nt][3]));
    }
    mA = fmaxf(mA, __shfl_xor_sync(~0u, mA, 1));
    mA = fmaxf(mA, __shfl_xor_sync(~0u, mA, 2));
    mB = fmaxf(mB, __shfl_xor_sync(~0u, mB, 1));
    mB = fmaxf(mB, __shfl_xor_sync(~0u, mB, 2));
    float sA = 0.f, sB = 0.f;
    #pragma unroll
    for (int nt = 0; nt < 8; nt++) {
        acc[nt][0] = __expf(acc[nt][0] - mA);
        acc[nt][1] = __expf(acc[nt][1] - mA);
        acc[nt][2] = __expf(acc[nt][2] - mB);
        acc[nt][3] = __expf(acc[nt][3] - mB);
        sA += acc[nt][0] + acc[nt][1];
        sB += acc[nt][2] + acc[nt][3];
    }
    sA += __shfl_xor_sync(~0u, sA, 1);
    sA += __shfl_xor_sync(~0u, sA, 2);
    sB += __shfl_xor_sync(~0u, sB, 1);
    sB += __shfl_xor_sync(~0u, sB, 2);
    float invA = 1.f / sA, invB = 1.f / sB;

    // ---- pack P fragments (C-layout -> A-layout, in registers) ----
    uint32_t pa[4][4];
    #pragma unroll
    for (int j = 0; j < 4; j++) {
        pa[j][0] = pack_bf2(acc[2*j][0]   * invA, acc[2*j][1]   * invA);
        pa[j][1] = pack_bf2(acc[2*j][2]   * invB, acc[2*j][3]   * invB);
        pa[j][2] = pack_bf2(acc[2*j+1][0] * invA, acc[2*j+1][1] * invA);
        pa[j][3] = pack_bf2(acc[2*j+1][2] * invB, acc[2*j+1][3] * invB);
    }

    // ---- O = P @ V : ldmatrix.trans on [tok][d] ----
    float oacc[4][4];
    #pragma unroll
    for (int i = 0; i < 4; i++)
        #pragma unroll
        for (int j = 0; j < 4; j++) oacc[i][j] = 0.f;

    int vrow = (lane & 7) | ((grp >> 1) << 3);
    int vcol = (grp & 1) * 8;
    #pragma unroll
    for (int j = 0; j < 4; j++) {
        #pragma unroll
        for (int dg = 0; dg < 2; dg++) {
            uint32_t bv[4];
            ldsm4t(bv[0], bv[1], bv[2], bv[3],
                   vB + (uint32_t)((j * 16 + vrow) * 40 + dg * 16 + vcol) * 2);
            mma16816(oacc[dg * 2 + 0], pa[j][0], pa[j][1], pa[j][2], pa[j][3], bv[0], bv[2]);
            mma16816(oacc[dg * 2 + 1], pa[j][0], pa[j][1], pa[j][2], pa[j][3], bv[1], bv[3]);
        }
    }

    // ---- write O (rows < 49) ----
    int rB = rA + 8;
    #pragma unroll
    for (int nd = 0; nd < 4; nd++) {
        int c = h * HD + nd * 8 + (lane & 3) * 2;
        if (rA < NTOK)
            *(__nv_bfloat162*)(obuf + ((size_t)w * NTOK + rA) * CC + c) =
                __floats2bfloat162_rn(oacc[nd][0], oacc[nd][1]);
        if (rB < NTOK)
            *(__nv_bfloat162*)(obuf + ((size_t)w * NTOK + rB) * CC + c) =
                __floats2bfloat162_rn(oacc[nd][2], oacc[nd][3]);
    }
}

// ---------------- launch --------------------------------------------------
extern "C" void kernel_launch(void* const* d_in, const int* in_sizes, int n_in,
                              void* d_out, int out_size)
{
    const float* x      = (const float*)d_in[0];
    const float* ln1_g  = (const float*)d_in[1];
    const float* ln1_b  = (const float*)d_in[2];
    const float* qkv_w  = (const float*)d_in[3];
    const float* qkv_b  = (const float*)d_in[4];
    const float* rpb    = (const float*)d_in[5];
    const float* proj_w = (const float*)d_in[6];
    const float* proj_b = (const float*)d_in[7];
    const float* ln2_g  = (const float*)d_in[8];
    const float* ln2_b  = (const float*)d_in[9];
    const float* fc1_w  = (const float*)d_in[10];
    const float* fc1_b  = (const float*)d_in[11];
    const float* fc2_w  = (const float*)d_in[12];
    const float* fc2_b  = (const float*)d_in[13];
    float* out = (float*)d_out;

    __nv_bfloat16 *hwin, *qkvb, *obuf, *act, *wq, *wp, *wf1, *wf2;
    float *x1, *bq, *bm;
    cudaGetSymbolAddress((void**)&hwin, g_hwin);
    cudaGetSymbolAddress((void**)&qkvb, g_qkv);
    cudaGetSymbolAddress((void**)&obuf, g_obuf);
    cudaGetSymbolAddress((void**)&x1,   g_x1);
    cudaGetSymbolAddress((void**)&act,  g_act);
    cudaGetSymbolAddress((void**)&wq,   g_wq);
    cudaGetSymbolAddress((void**)&wp,   g_wp);
    cudaGetSymbolAddress((void**)&wf1,  g_wf1);
    cudaGetSymbolAddress((void**)&wf2,  g_wf2);
    cudaGetSymbolAddress((void**)&bq,   g_bq);
    cudaGetSymbolAddress((void**)&bm,   g_bm);

    // 0) weight conversions + fused bias/mask table
    f2bf_all<<<768, 256>>>(qkv_w, proj_w, fc1_w, fc2_w, qkv_b, wq, wp, wf1, wf2, bq);
    bm_init<<<256, 256>>>(rpb, bm);

    // 1) LN1 + shift + window gather
    ln_kernel<<<MROWS / 8, 256>>>(x, hwin, ln1_g, ln1_b, 1);
    // 2) QKV projection (bf16 out, q pre-scaled)
    hgemm<0><<<dim3(MROWS / 128, 3), 256>>>(hwin, wq, bq, qkvb, nullptr, MROWS, 3*CC, CC);
    // 3) tensor-core window attention
    attn_tc<<<TOTW * NH, 128>>>(qkvb, bm, obuf);
    // 4) proj + scatter + residual -> x1 fp32
    hgemm<1><<<dim3(MROWS / 128, 1), 256>>>(obuf, wp, proj_b, x1, x, MROWS, CC, CC);
    // 5) LN2
    ln_kernel<<<MROWS / 8, 256>>>(x1, hwin, ln2_g, ln2_b, 0);
    // 6) fc1 + GELU (bf16 out)
    hgemm<2><<<dim3(MROWS / 128, MLPH / 128), 256>>>(hwin, wf1, fc1_b, act, nullptr, MROWS, MLPH, CC);
    // 7) fc2 + residual -> final fp32
    hgemm<3><<<dim3(MROWS / 128, 1), 256>>>(act, wf2, fc2_b, out, x1, MROWS, CC, MLPH);
}